// round 13
// baseline (speedup 1.0000x reference)
#include <cuda_runtime.h>
#include <cuda_fp16.h>
#include <cstdint>
#include <math.h>

#define Bb 8
#define Tt 512
#define Cc 256
#define Kk 4
constexpr int BT    = Bb * Tt;     // 4096
constexpr int NPROJ = 1792;        // [q|k|qs|v|mq|mk|mv]
constexpr float NEGV = -1e22f;

constexpr long sTT  = (long)Tt * Tt;
constexpr long sTQ  = (long)Tt * 768;
constexpr long sT5  = (long)Tt * 512;
constexpr long sTLD = (long)Tt * 1024;
constexpr long sTC  = (long)Tt * Cc;
constexpr long sVT  = (long)Cc * 1024;
constexpr long OUTN = (long)BT * Cc;          // 1M elements

// ---- scratch -----------------------------------------------------------
__device__ __half gh_Wall[NPROJ * Cc];        // B-side only: hi only
__device__ __half gh_x[BT * Cc];
__device__ __half gl_x[BT * Cc];
__device__ int    g_idx [BT * Kk];
__device__ float  g_proj[(long)BT * NPROJ];
__device__ __half gh_qmm[(long)BT * 768];   // [q|mq|mk]
__device__ __half gl_qmm[(long)BT * 768];
__device__ __half gh_A2[(long)BT * 512];
__device__ __half gl_A2[(long)BT * 512];
__device__ __half gh_B2[(long)BT * 512];      // B-side only
__device__ float  g_Gq [(long)Bb * Tt * Tt];
__device__ float  g_LD [(long)BT * 1024];   // logits [L|D]
__device__ __half gh_P [(long)BT * 1024];
__device__ __half gl_P [(long)BT * 1024];
__device__ __half gh_Vt[(long)Bb * Cc * 1024];  // B-side only
__device__ float  g_part[4 * OUTN];         // split-K partials

// ---- PTX helpers -------------------------------------------------------
__device__ __forceinline__ uint32_t smem_u32(const void* p) {
    uint32_t a;
    asm("{ .reg .u64 t; cvta.to.shared.u64 t, %1; cvt.u32.u64 %0, t; }" : "=r"(a) : "l"(p));
    return a;
}
__device__ __forceinline__ void cp16(uint32_t s, const void* g) {
    asm volatile("cp.async.cg.shared.global [%0], [%1], 16;" :: "r"(s), "l"(g));
}
__device__ __forceinline__ void cp_commit() {
    asm volatile("cp.async.commit_group;" ::: "memory");
}
__device__ __forceinline__ void cp_wait1() {
    asm volatile("cp.async.wait_group 1;" ::: "memory");
}
__device__ __forceinline__ void ldsm4(uint32_t& r0, uint32_t& r1, uint32_t& r2,
                                      uint32_t& r3, uint32_t a) {
    asm volatile("ldmatrix.sync.aligned.m8n8.x4.shared.b16 {%0,%1,%2,%3}, [%4];"
                 : "=r"(r0), "=r"(r1), "=r"(r2), "=r"(r3) : "r"(a));
}
__device__ __forceinline__ void mma_f16(float* c, uint32_t a0, uint32_t a1, uint32_t a2,
                                        uint32_t a3, uint32_t b0, uint32_t b1) {
    asm volatile(
        "mma.sync.aligned.m16n8k16.row.col.f32.f16.f16.f32 "
        "{%0,%1,%2,%3}, {%4,%5,%6,%7}, {%8,%9}, {%0,%1,%2,%3};\n"
        : "+f"(c[0]), "+f"(c[1]), "+f"(c[2]), "+f"(c[3])
        : "r"(a0), "r"(a1), "r"(a2), "r"(a3), "r"(b0), "r"(b1));
}
__device__ __forceinline__ void split1(float v, __half* h, __half* l) {
    __half hh = __float2half_rn(v);
    *h = hh;
    *l = __float2half_rn(v - __half2float(hh));
}

// ---- fp16x2 tensor-core NT GEMM core -----------------------------------
// A pre-split hi/lo; B rounded to fp16 hi only: c += ah*bh ; c += al*bh.
// 512 threads, CTA tile 128x128 (4x4 warps of 32x32), BK=64, 3-stage ring.
// C[m,n] = alpha * sum_k A[m,k]*B[n,k]; flags: 1 = adj mask
constexpr int HSTR    = 72;                  // 64 + 8 pad halves per smem row
constexpr int TILE_B  = 128 * HSTR * 2;      // 18432 B
constexpr int STAGE_B = 3 * TILE_B;          // Ah,Al,Bh = 55296 B
constexpr int NSTAGE  = 3;
constexpr int SMEM_DYN = NSTAGE * STAGE_B;   // 165888 B

__device__ __forceinline__ void gemm_core(
    const __half* __restrict__ Ah, const __half* __restrict__ Al,
    const __half* __restrict__ Bh,
    float* __restrict__ C, int nch, int lda, int ldb, int ldc, float alpha,
    const float* __restrict__ mask, int ldm, int flags, int m0, int n0, char* sm) {
    uint32_t sm32 = smem_u32(sm);
    int tid = threadIdx.x;
    int wid = tid >> 5, lane = tid & 31;
    int wm = wid >> 2, wn = wid & 3;             // 4x4 warp grid, 32x32 tiles
    int lr = lane >> 2, lc = lane & 3;

    int ldrow = tid >> 2;                        // 0..127
    int ldc16 = (tid & 3) * 16;                  // halves 0,16,32,48

    int aRow = wm * 32 + (lane & 15);
    int aK8  = (lane >> 4) * 8;
    int quad = lane >> 3, rb = lane & 7;
    int bRow = wn * 32 + (quad >> 1) * 8 + rb;
    int bK8  = (quad & 1) * 8;

    float c[2][4][4];
#pragma unroll
    for (int i = 0; i < 2; i++)
#pragma unroll
        for (int j = 0; j < 4; j++)
#pragma unroll
            for (int e = 0; e < 4; e++) c[i][j][e] = 0.f;

    auto issue = [&](int it) {
        uint32_t base = sm32 + (it % NSTAGE) * STAGE_B;
        int k0 = it * 64;
        uint32_t dst = base + (ldrow * HSTR + ldc16) * 2;
        const __half* pAh = Ah + (long)(m0 + ldrow) * lda + k0 + ldc16;
        const __half* pAl = Al + (long)(m0 + ldrow) * lda + k0 + ldc16;
        const __half* pBh = Bh + (long)(n0 + ldrow) * ldb + k0 + ldc16;
        cp16(dst, pAh);               cp16(dst + 16, pAh + 8);
        cp16(dst + TILE_B, pAl);      cp16(dst + TILE_B + 16, pAl + 8);
        cp16(dst + 2 * TILE_B, pBh);  cp16(dst + 2 * TILE_B + 16, pBh + 8);
    };

    issue(0); cp_commit();
    issue(1); cp_commit();
    for (int it = 0; it < nch; it++) {
        cp_wait1();                 // stage it resident
        __syncthreads();            // all warps done reading buffer (it-1)%3
        if (it + 2 < nch) issue(it + 2);
        cp_commit();
        uint32_t base = sm32 + (it % NSTAGE) * STAGE_B;
        uint32_t aAddr = base + (aRow * HSTR + aK8) * 2;
        uint32_t bAddr = base + 2 * TILE_B + (bRow * HSTR + bK8) * 2;
#pragma unroll
        for (int ks = 0; ks < 4; ks++) {
            uint32_t ah[2][4], al[2][4], bh[4][2];
#pragma unroll
            for (int mt = 0; mt < 2; mt++) {
                uint32_t a = aAddr + mt * (16 * HSTR * 2) + ks * 32;
                ldsm4(ah[mt][0], ah[mt][1], ah[mt][2], ah[mt][3], a);
                ldsm4(al[mt][0], al[mt][1], al[mt][2], al[mt][3], a + TILE_B);
            }
#pragma unroll
            for (int np = 0; np < 2; np++) {
                uint32_t b = bAddr + np * (16 * HSTR * 2) + ks * 32;
                ldsm4(bh[2 * np][0], bh[2 * np][1], bh[2 * np + 1][0], bh[2 * np + 1][1], b);
            }
            // pass 1: ah*bh — 8 independent accumulators
#pragma unroll
            for (int mt = 0; mt < 2; mt++)
#pragma unroll
                for (int nt = 0; nt < 4; nt++)
                    mma_f16(c[mt][nt], ah[mt][0], ah[mt][1], ah[mt][2], ah[mt][3],
                            bh[nt][0], bh[nt][1]);
            // pass 2: al*bh
#pragma unroll
            for (int mt = 0; mt < 2; mt++)
#pragma unroll
                for (int nt = 0; nt < 4; nt++)
                    mma_f16(c[mt][nt], al[mt][0], al[mt][1], al[mt][2], al[mt][3],
                            bh[nt][0], bh[nt][1]);
        }
    }

    // epilogue
#pragma unroll
    for (int mt = 0; mt < 2; mt++) {
        int gm = m0 + wm * 32 + mt * 16 + lr;
#pragma unroll
        for (int nt = 0; nt < 4; nt++) {
            int gn = n0 + wn * 32 + nt * 8 + 2 * lc;
#pragma unroll
            for (int half = 0; half < 2; half++) {
                int row = gm + half * 8;
                float v0 = c[mt][nt][2 * half + 0] * alpha;
                float v1 = c[mt][nt][2 * half + 1] * alpha;
                if (flags & 1) {
                    const float2 a = *(const float2*)(mask + (long)row * ldm + gn);
                    if (a.x == 0.0f) v0 += NEGV;
                    if (a.y == 0.0f) v1 += NEGV;
                }
                *(float2*)(C + (long)row * ldc + gn) = make_float2(v0, v1);
            }
        }
    }
}

// ---- proj GEMM: x @ Wall^T --------------------------------------------
__global__ void __launch_bounds__(512)
gemm_proj() {
    extern __shared__ char sm[];
    gemm_core(gh_x, gl_x, gh_Wall, g_proj, Cc / 64, Cc, Cc, NPROJ,
              1.0f, nullptr, 0, 0, blockIdx.y * 128, blockIdx.x * 128, sm);
}

// ---- mid GEMMs merged: job0=L(+mask) job1=Gq job2=D --------------------
__global__ void __launch_bounds__(512)
gemm_mid(const float* __restrict__ adj) {
    extern __shared__ char sm[];
    int job = blockIdx.z >> 3, b = blockIdx.z & 7;
    int m0 = blockIdx.y * 128, n0 = blockIdx.x * 128;
    if (job == 0) {
        gemm_core(gh_A2 + b * sT5, gl_A2 + b * sT5, gh_B2 + b * sT5,
                  g_LD + b * sTLD, 8, 512, 512, 1024, 1.0f,
                  adj + b * sTT, Tt, 1, m0, n0, sm);
    } else if (job == 1) {
        gemm_core(gh_qmm + b * sTQ, gl_qmm + b * sTQ, gh_qmm + b * sTQ,
                  g_Gq + b * sTT, 4, 768, 768, 512, 1.0f,
                  nullptr, 0, 0, m0, n0, sm);
    } else {
        gemm_core(gh_qmm + b * sTQ + 256, gl_qmm + b * sTQ + 256,
                  gh_qmm + b * sTQ + 512,
                  g_LD + b * sTLD + 512, 4, 768, 768, 1024, 0.0625f,
                  nullptr, 0, 0, m0, n0, sm);
    }
}

// ---- output GEMM split-K: slice s covers k in [s*256, s*256+256) -------
__global__ void __launch_bounds__(512)
gemm_out() {
    extern __shared__ char sm[];
    int s = blockIdx.z >> 3, b = blockIdx.z & 7;
    gemm_core(gh_P + b * sTLD + s * 256, gl_P + b * sTLD + s * 256,
              gh_Vt + b * sVT + s * 256,
              g_part + (long)s * OUTN + b * sTC, 4, 1024, 1024, Cc, 1.0f,
              nullptr, 0, 0, blockIdx.y * 128, blockIdx.x * 128, sm);
}

// ---- reduce 4 partials into out (deterministic order) ------------------
__global__ void reduce_out(float* __restrict__ out) {
    long i = (long)(blockIdx.x * blockDim.x + threadIdx.x) * 4;
    if (i >= OUTN) return;
    const float4 p0 = *(const float4*)(g_part + i);
    const float4 p1 = *(const float4*)(g_part + OUTN + i);
    const float4 p2 = *(const float4*)(g_part + 2 * OUTN + i);
    const float4 p3 = *(const float4*)(g_part + 3 * OUTN + i);
    *(float4*)(out + i) = make_float4((p0.x + p1.x) + (p2.x + p3.x),
                                      (p0.y + p1.y) + (p2.y + p3.y),
                                      (p0.z + p1.z) + (p2.z + p3.z),
                                      (p0.w + p1.w) + (p2.w + p3.w));
}

// ---- pack weights -> hi fp16 -------------------------------------------
__global__ void pack_w(const float* __restrict__ Wq, const float* __restrict__ Wk,
                       const float* __restrict__ Wqs, const float* __restrict__ Wv,
                       const float* __restrict__ Wqkv, __half* __restrict__ Wh) {
    int i = blockIdx.x * blockDim.x + threadIdx.x;
    if (i >= NPROJ * Cc) return;
    int row = i / Cc, col = i % Cc;
    float v;
    if      (row <  256) v = Wq  [ row         * Cc + col];
    else if (row <  512) v = Wk  [(row -  256) * Cc + col];
    else if (row <  768) v = Wqs [(row -  512) * Cc + col];
    else if (row < 1024) v = Wv  [(row -  768) * Cc + col];
    else                 v = Wqkv[(row - 1024) * Cc + col];
    Wh[i] = __float2half_rn(v);
}

// ---- x -> hi/lo fp16 ----------------------------------------------------
__global__ void conv_x(const float* __restrict__ x, __half* __restrict__ xh,
                       __half* __restrict__ xl) {
    int i = blockIdx.x * blockDim.x + threadIdx.x;
    if (i >= BT * Cc) return;
    split1(x[i], xh + i, xl + i);
}

// ---- idx from one-hot (warp per row) -----------------------------------
__global__ void extract_idx(const float* __restrict__ inxs, int* __restrict__ idx) {
    int w = (blockIdx.x * blockDim.x + threadIdx.x) >> 5;
    int lane = threadIdx.x & 31;
    if (w >= BT * Kk) return;
    const float4* p = (const float4*)(inxs + (long)w * Tt);
    int found = 0;
    for (int j = lane; j < Tt / 4; j += 32) {
        float4 v = p[j];
        if (v.x > 0.5f) found = 4 * j;
        if (v.y > 0.5f) found = 4 * j + 1;
        if (v.z > 0.5f) found = 4 * j + 2;
        if (v.w > 0.5f) found = 4 * j + 3;
    }
#pragma unroll
    for (int d = 16; d > 0; d >>= 1)
        found = max(found, __shfl_xor_sync(0xffffffffu, found, d));
    if (lane == 0) idx[w] = found;
}

// ---- normalize q,k,qs; emit hi/lo for q,mq,mk --------------------------
__global__ void prep_proj(float* __restrict__ proj, __half* __restrict__ qh,
                          __half* __restrict__ ql) {
    long row = blockIdx.x;
    int tid = threadIdx.x;
    __shared__ float red[8];
    __shared__ float bcast;
    for (int seg = 0; seg < 3; seg++) {
        long o = row * NPROJ + seg * 256 + tid;
        float v = proj[o];
        float ss = v * v;
#pragma unroll
        for (int d = 16; d > 0; d >>= 1) ss += __shfl_xor_sync(0xffffffffu, ss, d);
        if ((tid & 31) == 0) red[tid >> 5] = ss;
        __syncthreads();
        if (tid == 0) {
            float s = 0.f;
            for (int i = 0; i < 8; i++) s += red[i];
            bcast = 1.0f / fmaxf(sqrtf(s), 1e-12f);
        }
        __syncthreads();
        float nv = v * bcast;
        proj[o] = nv;
        if (seg == 0) split1(nv, qh + row * 768 + tid, ql + row * 768 + tid);
        __syncthreads();
    }
    float mq = proj[row * NPROJ + 1024 + tid];
    float mk = proj[row * NPROJ + 1280 + tid];
    split1(mq, qh + row * 768 + 256 + tid, ql + row * 768 + 256 + tid);
    split1(mk, qh + row * 768 + 512 + tid, ql + row * 768 + 512 + tid);
}

// ---- build [qs|kn_sum] hi/lo and [qs|k] hi ------------------------------
__global__ void build_ab(const float* __restrict__ proj, const int* __restrict__ idx,
                         __half* __restrict__ A2h, __half* __restrict__ A2l,
                         __half* __restrict__ B2h,
                         const float* __restrict__ ns_w) {
    int row = blockIdx.x;
    int c = threadIdx.x;
    int b = row >> 9;
    long pbase = (long)row * NPROJ;
    float qs = proj[pbase + 512 + c];
    float kv = proj[pbase + 256 + c];
    long o = (long)row * 512;
    B2h[o + c] = __float2half_rn(qs);
    B2h[o + 256 + c] = __float2half_rn(kv);
    split1(qs, A2h + o + c, A2l + o + c);
    float s = 0.f;
#pragma unroll
    for (int n = 0; n < Kk; n++) {
        int t = idx[row * Kk + n];
        s += ns_w[n] * proj[((long)(b * Tt + t)) * NPROJ + 256 + c];
    }
    split1(s, A2h + o + 256 + c, A2l + o + 256 + c);
}

// ---- transpose v/mv into hi [b][c][ v_t | mv_t ] -----------------------
__global__ void transpose_v(const float* __restrict__ proj, __half* __restrict__ Vh) {
    __shared__ float tile[32][33];
    int which = blockIdx.z >> 3;
    int b = blockIdx.z & 7;
    int t0 = blockIdx.x * 32, c0 = blockIdx.y * 32;
    int tx = threadIdx.x & 31, ty = threadIdx.x >> 5;
    int srcCol = (which ? 1536 : 768) + c0;
    for (int i = ty; i < 32; i += 8)
        tile[i][tx] = proj[((long)(b * Tt + t0 + i)) * NPROJ + srcCol + tx];
    __syncthreads();
    long dbase = ((long)b * Cc + c0) * 1024 + which * 512 + t0;
    for (int i = ty; i < 32; i += 8)
        Vh[dbase + (long)i * 1024 + tx] = __float2half_rn(tile[tx][i]);
}

// ---- fused sim_nn + L softmax + D softmax -> Ph/Pl ---------------------
__global__ void simnn_softmax(const float* __restrict__ Gq, const int* __restrict__ idx,
                              const float* __restrict__ LD, const float* __restrict__ nn_w,
                              __half* __restrict__ Ph, __half* __restrict__ Pl) {
    int i = blockIdx.x, b = blockIdx.y;
    int tid = threadIdx.x;
    __shared__ float srow[4][Tt];
    __shared__ int   sjdx[Tt * Kk];
    __shared__ float w[4];
    __shared__ float red[8];
    __shared__ float bcast;
    if (tid < 4) w[tid] = nn_w[tid];
    for (int j = tid; j < Tt * Kk; j += 256) sjdx[j] = idx[b * Tt * Kk + j];
#pragma unroll
    for (int x = 0; x < 4; x++) {
        int rx = idx[(b * Tt + i) * Kk + x];
        for (int c = tid; c < Tt; c += 256)
            srow[x][c] = Gq[((long)b * Tt + rx) * Tt + c];
    }
    __syncthreads();
    long base = ((long)b * Tt + i) * 1024;
    // ---- L half: logits + sim_nn, softmax ----
    float2 v = ((const float2*)(LD + base))[tid];
#pragma unroll
    for (int half = 0; half < 2; half++) {
        int j = 2 * tid + half;
        float acc = 0.f;
#pragma unroll
        for (int x = 0; x < 4; x++) {
            float m = -3.4e38f;
#pragma unroll
            for (int y = 0; y < 4; y++)
                m = fmaxf(m, srow[x][sjdx[j * Kk + y]]);
            acc += w[x] * m;
        }
        if (half == 0) v.x += acc; else v.y += acc;
    }
    float m = fmaxf(v.x, v.y);
#pragma unroll
    for (int d = 16; d > 0; d >>= 1) m = fmaxf(m, __shfl_xor_sync(0xffffffffu, m, d));
    if ((tid & 31) == 0) red[tid >> 5] = m;
    __syncthreads();
    if (tid == 0) {
        float mm = red[0];
        for (int k = 1; k < 8; k++) mm = fmaxf(mm, red[k]);
        bcast = mm;
    }
    __syncthreads();
    float mm = bcast;
    float e0 = __expf(v.x - mm), e1 = __expf(v.y - mm);
    float s = e0 + e1;
#pragma unroll
    for (int d = 16; d > 0; d >>= 1) s += __shfl_xor_sync(0xffffffffu, s, d);
    if ((tid & 31) == 0) red[tid >> 5] = s;
    __syncthreads();
    if (tid == 0) {
        float ss = 0.f;
        for (int k = 0; k < 8; k++) ss += red[k];
        bcast = 1.0f / ss;
    }
    __syncthreads();
    float inv = bcast;
    split1(e0 * inv, Ph + base + 2 * tid, Pl + base + 2 * tid);
    split1(e1 * inv, Ph + base + 2 * tid + 1, Pl + base + 2 * tid + 1);
    __syncthreads();
    // ---- D half: plain softmax ----
    float2 vd = ((const float2*)(LD + base + 512))[tid];
    float md = fmaxf(vd.x, vd.y);
#pragma unroll
    for (int d = 16; d > 0; d >>= 1) md = fmaxf(md, __shfl_xor_sync(0xffffffffu, md, d));
    if ((tid & 31) == 0) red[tid >> 5] = md;
    __syncthreads();
    if (tid == 0) {
        float mm2 = red[0];
        for (int k = 1; k < 8; k++) mm2 = fmaxf(mm2, red[k]);
        bcast = mm2;
    }
    __syncthreads();
    float mm2 = bcast;
    float f0 = __expf(vd.x - mm2), f1 = __expf(vd.y - mm2);
    float sd = f0 + f1;
#pragma unroll
    for (int d = 16; d > 0; d >>= 1) sd += __shfl_xor_sync(0xffffffffu, sd, d);
    if ((tid & 31) == 0) red[tid >> 5] = sd;
    __syncthreads();
    if (tid == 0) {
        float ss = 0.f;
        for (int k = 0; k < 8; k++) ss += red[k];
        bcast = 1.0f / ss;
    }
    __syncthreads();
    float invd = bcast;
    split1(f0 * invd, Ph + base + 512 + 2 * tid, Pl + base + 512 + 2 * tid);
    split1(f1 * invd, Ph + base + 512 + 2 * tid + 1, Pl + base + 512 + 2 * tid + 1);
}

// ---- host --------------------------------------------------------------
extern "C" void kernel_launch(void* const* d_in, const int* in_sizes, int n_in,
                              void* d_out, int out_size) {
    const float* x    = (const float*)d_in[0];
    const float* adj  = (const float*)d_in[1];
    const float* inxs = (const float*)d_in[2];
    const float* Wq   = (const float*)d_in[3];
    const float* Wk   = (const float*)d_in[4];
    const float* Wqs  = (const float*)d_in[5];
    const float* Wv   = (const float*)d_in[6];
    const float* nn_w = (const float*)d_in[7];
    const float* ns_w = (const float*)d_in[8];
    const float* Wqkv = (const float*)d_in[9];
    float* out = (float*)d_out;

    __half *pWh, *pxh, *pxl, *pqh, *pql, *pA2h, *pA2l, *pB2h;
    __half *pPh, *pPl, *pVh;
    float *pProj, *pGq, *pLD; int* pIdx;
    cudaGetSymbolAddress((void**)&pWh,  gh_Wall);
    cudaGetSymbolAddress((void**)&pxh,  gh_x);
    cudaGetSymbolAddress((void**)&pxl,  gl_x);
    cudaGetSymbolAddress((void**)&pIdx, g_idx);
    cudaGetSymbolAddress((void**)&pProj, g_proj);
    cudaGetSymbolAddress((void**)&pqh,  gh_qmm);
    cudaGetSymbolAddress((void**)&pql,  gl_qmm);
    cudaGetSymbolAddress((void**)&pA2h, gh_A2);
    cudaGetSymbolAddress((void**)&pA2l, gl_A2);
    cudaGetSymbolAddress((void**)&pB2h, gh_B2);
    cudaGetSymbolAddress((void**)&pGq,  g_Gq);
    cudaGetSymbolAddress((void**)&pLD,  g_LD);
    cudaGetSymbolAddress((void**)&pPh,  gh_P);
    cudaGetSymbolAddress((void**)&pPl,  gl_P);
    cudaGetSymbolAddress((void**)&pVh,  gh_Vt);

    cudaFuncSetAttribute(gemm_proj, cudaFuncAttributeMaxDynamicSharedMemorySize, SMEM_DYN);
    cudaFuncSetAttribute(gemm_mid,  cudaFuncAttributeMaxDynamicSharedMemorySize, SMEM_DYN);
    cudaFuncSetAttribute(gemm_out,  cudaFuncAttributeMaxDynamicSharedMemorySize, SMEM_DYN);

    pack_w<<<(NPROJ * Cc + 255) / 256, 256>>>(Wq, Wk, Wqs, Wv, Wqkv, pWh);
    conv_x<<<(BT * Cc + 255) / 256, 256>>>(x, pxh, pxl);
    extract_idx<<<(BT * Kk * 32 + 255) / 256, 256>>>(inxs, pIdx);

    // proj = x @ Wall^T : (4096 x 1792), K=256
    gemm_proj<<<dim3(NPROJ / 128, BT / 128, 1), 512, SMEM_DYN>>>();

    transpose_v<<<dim3(Tt / 32, Cc / 32, 2 * Bb), 256>>>(pProj, pVh);
    prep_proj<<<BT, 256>>>(pProj, pqh, pql);
    build_ab<<<BT, 256>>>(pProj, pIdx, pA2h, pA2l, pB2h, ns_w);

    // merged: L(+mask), Gq, D  — grid 4x4x24
    gemm_mid<<<dim3(4, 4, 24), 512, SMEM_DYN>>>(adj);

    simnn_softmax<<<dim3(Tt, Bb), 256>>>(pGq, pIdx, pLD, nn_w, pPh, pPl);

    // out: split-K=4 partials then reduce
    gemm_out<<<dim3(Cc / 128, Tt / 128, 32), 512, SMEM_DYN>>>();
    reduce_out<<<(int)(OUTN / 4 + 255) / 256, 256>>>(out);
}

// round 14
// speedup vs baseline: 1.1139x; 1.1139x over previous
#include <cuda_runtime.h>
#include <cuda_fp16.h>
#include <cstdint>
#include <math.h>

#define Bb 8
#define Tt 512
#define Cc 256
#define Kk 4
constexpr int BT    = Bb * Tt;     // 4096
constexpr int NPROJ = 1792;        // [q|k|qs|v|mq|mk|mv]
constexpr float NEGV = -1e22f;

constexpr long sTT  = (long)Tt * Tt;
constexpr long sTQ  = (long)Tt * 768;
constexpr long sT5  = (long)Tt * 512;
constexpr long sTLD = (long)Tt * 1024;
constexpr long sTC  = (long)Tt * Cc;
constexpr long sVT  = (long)Cc * 1024;
constexpr long OUTN = (long)BT * Cc;          // 1M elements

// ---- scratch -----------------------------------------------------------
__device__ __half gh_Wall[NPROJ * Cc];        // B-side: hi only
__device__ __half gh_x[BT * Cc];
__device__ __half gl_x[BT * Cc];
__device__ int    g_idx [BT * Kk];
__device__ float  g_proj[(long)BT * NPROJ];
__device__ __half gh_qmm[(long)BT * 768];   // [q|mq|mk]
__device__ __half gl_qmm[(long)BT * 768];
__device__ __half gh_A2[(long)BT * 512];
__device__ __half gl_A2[(long)BT * 512];
__device__ __half gh_B2[(long)BT * 512];      // B-side only
__device__ float  g_Gq [(long)Bb * Tt * Tt];
__device__ float  g_LD [(long)BT * 1024];   // logits [L|D]
__device__ __half gh_P [(long)BT * 1024];   // probs (single fp16)
__device__ __half gh_Vt[(long)Bb * Cc * 1024];  // B-side only
__device__ float  g_part[4 * OUTN];         // split-K partials

// ---- PTX helpers -------------------------------------------------------
__device__ __forceinline__ uint32_t smem_u32(const void* p) {
    uint32_t a;
    asm("{ .reg .u64 t; cvta.to.shared.u64 t, %1; cvt.u32.u64 %0, t; }" : "=r"(a) : "l"(p));
    return a;
}
__device__ __forceinline__ void cp16(uint32_t s, const void* g) {
    asm volatile("cp.async.cg.shared.global [%0], [%1], 16;" :: "r"(s), "l"(g));
}
__device__ __forceinline__ void cp_commit() {
    asm volatile("cp.async.commit_group;" ::: "memory");
}
__device__ __forceinline__ void cp_wait1() {
    asm volatile("cp.async.wait_group 1;" ::: "memory");
}
__device__ __forceinline__ void ldsm4(uint32_t& r0, uint32_t& r1, uint32_t& r2,
                                      uint32_t& r3, uint32_t a) {
    asm volatile("ldmatrix.sync.aligned.m8n8.x4.shared.b16 {%0,%1,%2,%3}, [%4];"
                 : "=r"(r0), "=r"(r1), "=r"(r2), "=r"(r3) : "r"(a));
}
__device__ __forceinline__ void mma_f16(float* c, uint32_t a0, uint32_t a1, uint32_t a2,
                                        uint32_t a3, uint32_t b0, uint32_t b1) {
    asm volatile(
        "mma.sync.aligned.m16n8k16.row.col.f32.f16.f16.f32 "
        "{%0,%1,%2,%3}, {%4,%5,%6,%7}, {%8,%9}, {%0,%1,%2,%3};\n"
        : "+f"(c[0]), "+f"(c[1]), "+f"(c[2]), "+f"(c[3])
        : "r"(a0), "r"(a1), "r"(a2), "r"(a3), "r"(b0), "r"(b1));
}
__device__ __forceinline__ void split1(float v, __half* h, __half* l) {
    __half hh = __float2half_rn(v);
    *h = hh;
    *l = __float2half_rn(v - __half2float(hh));
}

// ---- fp16 tensor-core NT GEMM core --------------------------------------
// useAl=1: c += ah*bh + al*bh (A split hi/lo, exact vs fp16-B)
// useAl=0: c += ah*bh only (A rounded once)
// 512 threads, CTA tile 128x128 (4x4 warps of 32x32), BK=32, 3-stage ring.
constexpr int HSTR    = 40;                  // padded halves per smem row
constexpr int TILE_B  = 128 * HSTR * 2;      // 10240 B
constexpr int STAGE_B = 3 * TILE_B;          // Ah,Al,Bh = 30720 B
constexpr int NSTAGE  = 3;
constexpr int SMEM_DYN = NSTAGE * STAGE_B;   // 92160 B

__device__ __forceinline__ void gemm_core(
    const __half* __restrict__ Ah, const __half* __restrict__ Al,
    const __half* __restrict__ Bh,
    float* __restrict__ C, int nch, int lda, int ldb, int ldc, float alpha,
    const float* __restrict__ mask, int ldm, int flags, int m0, int n0, char* sm,
    int useAl) {
    uint32_t sm32 = smem_u32(sm);
    int tid = threadIdx.x;
    int wid = tid >> 5, lane = tid & 31;
    int wm = wid >> 2, wn = wid & 3;             // 4x4 warp grid, 32x32 tiles
    int lr = lane >> 2, lc = lane & 3;

    int ldrow = tid >> 2;                        // 0..127
    int ldc8  = (tid & 3) * 8;

    int aRow = wm * 32 + (lane & 15);
    int aK8  = (lane >> 4) * 8;
    int quad = lane >> 3, rb = lane & 7;
    int bRow = wn * 32 + (quad >> 1) * 8 + rb;
    int bK8  = (quad & 1) * 8;

    float c[2][4][4];
#pragma unroll
    for (int i = 0; i < 2; i++)
#pragma unroll
        for (int j = 0; j < 4; j++)
#pragma unroll
            for (int e = 0; e < 4; e++) c[i][j][e] = 0.f;

    auto issue = [&](int it) {
        uint32_t base = sm32 + (it % NSTAGE) * STAGE_B;
        int k0 = it * 32;
        uint32_t dst = base + (ldrow * HSTR + ldc8) * 2;
        cp16(dst, Ah + (long)(m0 + ldrow) * lda + k0 + ldc8);
        if (useAl) cp16(dst + TILE_B, Al + (long)(m0 + ldrow) * lda + k0 + ldc8);
        cp16(dst + 2 * TILE_B, Bh + (long)(n0 + ldrow) * ldb + k0 + ldc8);
    };

    issue(0); cp_commit();
    issue(1); cp_commit();
    for (int it = 0; it < nch; it++) {
        cp_wait1();                 // stage it resident
        __syncthreads();            // all warps done reading buffer (it-1)%3
        if (it + 2 < nch) issue(it + 2);
        cp_commit();
        uint32_t base = sm32 + (it % NSTAGE) * STAGE_B;
        uint32_t aAddr = base + (aRow * HSTR + aK8) * 2;
        uint32_t bAddr = base + 2 * TILE_B + (bRow * HSTR + bK8) * 2;
#pragma unroll
        for (int ks = 0; ks < 2; ks++) {
            uint32_t ah[2][4], al[2][4], bh[4][2];
#pragma unroll
            for (int mt = 0; mt < 2; mt++) {
                uint32_t a = aAddr + mt * (16 * HSTR * 2) + ks * 32;
                ldsm4(ah[mt][0], ah[mt][1], ah[mt][2], ah[mt][3], a);
                if (useAl) ldsm4(al[mt][0], al[mt][1], al[mt][2], al[mt][3], a + TILE_B);
            }
#pragma unroll
            for (int np = 0; np < 2; np++) {
                uint32_t b = bAddr + np * (16 * HSTR * 2) + ks * 32;
                ldsm4(bh[2 * np][0], bh[2 * np][1], bh[2 * np + 1][0], bh[2 * np + 1][1], b);
            }
#pragma unroll
            for (int mt = 0; mt < 2; mt++)
#pragma unroll
                for (int nt = 0; nt < 4; nt++)
                    mma_f16(c[mt][nt], ah[mt][0], ah[mt][1], ah[mt][2], ah[mt][3],
                            bh[nt][0], bh[nt][1]);
            if (useAl) {
#pragma unroll
                for (int mt = 0; mt < 2; mt++)
#pragma unroll
                    for (int nt = 0; nt < 4; nt++)
                        mma_f16(c[mt][nt], al[mt][0], al[mt][1], al[mt][2], al[mt][3],
                                bh[nt][0], bh[nt][1]);
            }
        }
    }

    // epilogue
#pragma unroll
    for (int mt = 0; mt < 2; mt++) {
        int gm = m0 + wm * 32 + mt * 16 + lr;
#pragma unroll
        for (int nt = 0; nt < 4; nt++) {
            int gn = n0 + wn * 32 + nt * 8 + 2 * lc;
#pragma unroll
            for (int half = 0; half < 2; half++) {
                int row = gm + half * 8;
                float v0 = c[mt][nt][2 * half + 0] * alpha;
                float v1 = c[mt][nt][2 * half + 1] * alpha;
                if (flags & 1) {
                    const float2 a = *(const float2*)(mask + (long)row * ldm + gn);
                    if (a.x == 0.0f) v0 += NEGV;
                    if (a.y == 0.0f) v1 += NEGV;
                }
                *(float2*)(C + (long)row * ldc + gn) = make_float2(v0, v1);
            }
        }
    }
}

// ---- proj GEMM: x @ Wall^T --------------------------------------------
__global__ void __launch_bounds__(512)
gemm_proj() {
    extern __shared__ char sm[];
    gemm_core(gh_x, gl_x, gh_Wall, g_proj, Cc / 32, Cc, Cc, NPROJ,
              1.0f, nullptr, 0, 0, blockIdx.y * 128, blockIdx.x * 128, sm, 1);
}

// ---- mid GEMMs merged: job0=L(+mask) job1=Gq job2=D --------------------
__global__ void __launch_bounds__(512)
gemm_mid(const float* __restrict__ adj) {
    extern __shared__ char sm[];
    int job = blockIdx.z >> 3, b = blockIdx.z & 7;
    int m0 = blockIdx.y * 128, n0 = blockIdx.x * 128;
    if (job == 0) {
        gemm_core(gh_A2 + b * sT5, gl_A2 + b * sT5, gh_B2 + b * sT5,
                  g_LD + b * sTLD, 16, 512, 512, 1024, 1.0f,
                  adj + b * sTT, Tt, 1, m0, n0, sm, 1);
    } else if (job == 1) {
        gemm_core(gh_qmm + b * sTQ, gl_qmm + b * sTQ, gh_qmm + b * sTQ,
                  g_Gq + b * sTT, 8, 768, 768, 512, 1.0f,
                  nullptr, 0, 0, m0, n0, sm, 1);
    } else {
        gemm_core(gh_qmm + b * sTQ + 256, gl_qmm + b * sTQ + 256,
                  gh_qmm + b * sTQ + 512,
                  g_LD + b * sTLD + 512, 8, 768, 768, 1024, 0.0625f,
                  nullptr, 0, 0, m0, n0, sm, 1);
    }
}

// ---- output GEMM split-K (P single-fp16, no lo pass) -------------------
__global__ void __launch_bounds__(512)
gemm_out() {
    extern __shared__ char sm[];
    int s = blockIdx.z >> 3, b = blockIdx.z & 7;
    gemm_core(gh_P + b * sTLD + s * 256, gh_P + b * sTLD + s * 256,
              gh_Vt + b * sVT + s * 256,
              g_part + (long)s * OUTN + b * sTC, 8, 1024, 1024, Cc, 1.0f,
              nullptr, 0, 0, blockIdx.y * 128, blockIdx.x * 128, sm, 0);
}

// ---- reduce 4 partials into out (deterministic order) ------------------
__global__ void reduce_out(float* __restrict__ out) {
    long i = (long)(blockIdx.x * blockDim.x + threadIdx.x) * 4;
    if (i >= OUTN) return;
    const float4 p0 = *(const float4*)(g_part + i);
    const float4 p1 = *(const float4*)(g_part + OUTN + i);
    const float4 p2 = *(const float4*)(g_part + 2 * OUTN + i);
    const float4 p3 = *(const float4*)(g_part + 3 * OUTN + i);
    *(float4*)(out + i) = make_float4((p0.x + p1.x) + (p2.x + p3.x),
                                      (p0.y + p1.y) + (p2.y + p3.y),
                                      (p0.z + p1.z) + (p2.z + p3.z),
                                      (p0.w + p1.w) + (p2.w + p3.w));
}

// ---- merged input prep: pack_w | conv_x | extract_idx ------------------
constexpr int NB_PACKW = (NPROJ * Cc) / 256;   // 1792
constexpr int NB_CONVX = (BT * Cc) / 256;      // 4096
constexpr int NB_EXIDX = (BT * Kk) / 8;        // 2048 (8 warps/block)
__global__ void prep_inputs(const float* __restrict__ Wq, const float* __restrict__ Wk,
                            const float* __restrict__ Wqs, const float* __restrict__ Wv,
                            const float* __restrict__ Wqkv, __half* __restrict__ Wh,
                            const float* __restrict__ x, __half* __restrict__ xh,
                            __half* __restrict__ xl,
                            const float* __restrict__ inxs, int* __restrict__ idx) {
    int blk = blockIdx.x;
    int tid = threadIdx.x;
    if (blk < NB_PACKW) {
        int i = blk * 256 + tid;
        int row = i / Cc, col = i % Cc;
        float v;
        if      (row <  256) v = Wq  [ row         * Cc + col];
        else if (row <  512) v = Wk  [(row -  256) * Cc + col];
        else if (row <  768) v = Wqs [(row -  512) * Cc + col];
        else if (row < 1024) v = Wv  [(row -  768) * Cc + col];
        else                 v = Wqkv[(row - 1024) * Cc + col];
        Wh[i] = __float2half_rn(v);
    } else if (blk < NB_PACKW + NB_CONVX) {
        int i = (blk - NB_PACKW) * 256 + tid;
        split1(x[i], xh + i, xl + i);
    } else {
        int w = ((blk - NB_PACKW - NB_CONVX) * 256 + tid) >> 5;
        int lane = tid & 31;
        const float4* p = (const float4*)(inxs + (long)w * Tt);
        int found = 0;
        for (int j = lane; j < Tt / 4; j += 32) {
            float4 v = p[j];
            if (v.x > 0.5f) found = 4 * j;
            if (v.y > 0.5f) found = 4 * j + 1;
            if (v.z > 0.5f) found = 4 * j + 2;
            if (v.w > 0.5f) found = 4 * j + 3;
        }
#pragma unroll
        for (int d = 16; d > 0; d >>= 1)
            found = max(found, __shfl_xor_sync(0xffffffffu, found, d));
        if (lane == 0) idx[w] = found;
    }
}

// ---- merged post-proj: transpose_v | prep_proj -------------------------
// transpose reads proj cols [768,1024)+[1536,1792); prep writes cols [0,768)
// and reads [1024,1536) — disjoint, safe in one launch.
constexpr int NB_TRV = (Tt / 32) * (Cc / 32) * 2 * Bb;  // 2048
__global__ void post_proj(float* __restrict__ proj, __half* __restrict__ Vh,
                          __half* __restrict__ qh, __half* __restrict__ ql) {
    int blk = blockIdx.x;
    int tid = threadIdx.x;
    if (blk < NB_TRV) {
        __shared__ float tile[32][33];
        int z = blk / 128, rem = blk % 128;
        int cy = rem / 16, txk = rem % 16;
        int which = z >> 3, b = z & 7;
        int t0 = txk * 32, c0 = cy * 32;
        int tx = tid & 31, ty = tid >> 5;
        int srcCol = (which ? 1536 : 768) + c0;
        for (int i = ty; i < 32; i += 8)
            tile[i][tx] = proj[((long)(b * Tt + t0 + i)) * NPROJ + srcCol + tx];
        __syncthreads();
        long dbase = ((long)b * Cc + c0) * 1024 + which * 512 + t0;
        for (int i = ty; i < 32; i += 8)
            Vh[dbase + (long)i * 1024 + tx] = __float2half_rn(tile[tx][i]);
    } else {
        long row = blk - NB_TRV;
        __shared__ float red[8];
        __shared__ float bcast;
        for (int seg = 0; seg < 3; seg++) {
            long o = row * NPROJ + seg * 256 + tid;
            float v = proj[o];
            float ss = v * v;
#pragma unroll
            for (int d = 16; d > 0; d >>= 1) ss += __shfl_xor_sync(0xffffffffu, ss, d);
            if ((tid & 31) == 0) red[tid >> 5] = ss;
            __syncthreads();
            if (tid == 0) {
                float s = 0.f;
                for (int i = 0; i < 8; i++) s += red[i];
                bcast = 1.0f / fmaxf(sqrtf(s), 1e-12f);
            }
            __syncthreads();
            float nv = v * bcast;
            proj[o] = nv;
            if (seg == 0) split1(nv, qh + row * 768 + tid, ql + row * 768 + tid);
            __syncthreads();
        }
        float mq = proj[row * NPROJ + 1024 + tid];
        float mk = proj[row * NPROJ + 1280 + tid];
        split1(mq, qh + row * 768 + 256 + tid, ql + row * 768 + 256 + tid);
        split1(mk, qh + row * 768 + 512 + tid, ql + row * 768 + 512 + tid);
    }
}

// ---- build [qs|kn_sum] hi/lo and [qs|k] hi ------------------------------
__global__ void build_ab(const float* __restrict__ proj, const int* __restrict__ idx,
                         __half* __restrict__ A2h, __half* __restrict__ A2l,
                         __half* __restrict__ B2h,
                         const float* __restrict__ ns_w) {
    int row = blockIdx.x;
    int c = threadIdx.x;
    int b = row >> 9;
    long pbase = (long)row * NPROJ;
    float qs = proj[pbase + 512 + c];
    float kv = proj[pbase + 256 + c];
    long o = (long)row * 512;
    B2h[o + c] = __float2half_rn(qs);
    B2h[o + 256 + c] = __float2half_rn(kv);
    split1(qs, A2h + o + c, A2l + o + c);
    float s = 0.f;
#pragma unroll
    for (int n = 0; n < Kk; n++) {
        int t = idx[row * Kk + n];
        s += ns_w[n] * proj[((long)(b * Tt + t)) * NPROJ + 256 + c];
    }
    split1(s, A2h + o + 256 + c, A2l + o + 256 + c);
}

// ---- fused sim_nn + L softmax + D softmax -> Ph ------------------------
__global__ void simnn_softmax(const float* __restrict__ Gq, const int* __restrict__ idx,
                              const float* __restrict__ LD, const float* __restrict__ nn_w,
                              __half* __restrict__ Ph) {
    int i = blockIdx.x, b = blockIdx.y;
    int tid = threadIdx.x;
    __shared__ float srow[4][Tt];
    __shared__ int   sjdx[Tt * Kk];
    __shared__ float w[4];
    __shared__ float red[8];
    __shared__ float bcast;
    if (tid < 4) w[tid] = nn_w[tid];
    for (int j = tid; j < Tt * Kk; j += 256) sjdx[j] = idx[b * Tt * Kk + j];
#pragma unroll
    for (int x = 0; x < 4; x++) {
        int rx = idx[(b * Tt + i) * Kk + x];
        for (int c = tid; c < Tt; c += 256)
            srow[x][c] = Gq[((long)b * Tt + rx) * Tt + c];
    }
    __syncthreads();
    long base = ((long)b * Tt + i) * 1024;
    // ---- L half ----
    float2 v = ((const float2*)(LD + base))[tid];
#pragma unroll
    for (int half = 0; half < 2; half++) {
        int j = 2 * tid + half;
        float acc = 0.f;
#pragma unroll
        for (int x = 0; x < 4; x++) {
            float m = -3.4e38f;
#pragma unroll
            for (int y = 0; y < 4; y++)
                m = fmaxf(m, srow[x][sjdx[j * Kk + y]]);
            acc += w[x] * m;
        }
        if (half == 0) v.x += acc; else v.y += acc;
    }
    float m = fmaxf(v.x, v.y);
#pragma unroll
    for (int d = 16; d > 0; d >>= 1) m = fmaxf(m, __shfl_xor_sync(0xffffffffu, m, d));
    if ((tid & 31) == 0) red[tid >> 5] = m;
    __syncthreads();
    if (tid == 0) {
        float mm = red[0];
        for (int k = 1; k < 8; k++) mm = fmaxf(mm, red[k]);
        bcast = mm;
    }
    __syncthreads();
    float mm = bcast;
    float e0 = __expf(v.x - mm), e1 = __expf(v.y - mm);
    float s = e0 + e1;
#pragma unroll
    for (int d = 16; d > 0; d >>= 1) s += __shfl_xor_sync(0xffffffffu, s, d);
    if ((tid & 31) == 0) red[tid >> 5] = s;
    __syncthreads();
    if (tid == 0) {
        float ss = 0.f;
        for (int k = 0; k < 8; k++) ss += red[k];
        bcast = 1.0f / ss;
    }
    __syncthreads();
    float inv = bcast;
    Ph[base + 2 * tid]     = __float2half_rn(e0 * inv);
    Ph[base + 2 * tid + 1] = __float2half_rn(e1 * inv);
    __syncthreads();
    // ---- D half ----
    float2 vd = ((const float2*)(LD + base + 512))[tid];
    float md = fmaxf(vd.x, vd.y);
#pragma unroll
    for (int d = 16; d > 0; d >>= 1) md = fmaxf(md, __shfl_xor_sync(0xffffffffu, md, d));
    if ((tid & 31) == 0) red[tid >> 5] = md;
    __syncthreads();
    if (tid == 0) {
        float mm2 = red[0];
        for (int k = 1; k < 8; k++) mm2 = fmaxf(mm2, red[k]);
        bcast = mm2;
    }
    __syncthreads();
    float mm2 = bcast;
    float f0 = __expf(vd.x - mm2), f1 = __expf(vd.y - mm2);
    float sd = f0 + f1;
#pragma unroll
    for (int d = 16; d > 0; d >>= 1) sd += __shfl_xor_sync(0xffffffffu, sd, d);
    if ((tid & 31) == 0) red[tid >> 5] = sd;
    __syncthreads();
    if (tid == 0) {
        float ss = 0.f;
        for (int k = 0; k < 8; k++) ss += red[k];
        bcast = 1.0f / ss;
    }
    __syncthreads();
    float invd = bcast;
    Ph[base + 512 + 2 * tid]     = __float2half_rn(f0 * invd);
    Ph[base + 512 + 2 * tid + 1] = __float2half_rn(f1 * invd);
}

// ---- host --------------------------------------------------------------
extern "C" void kernel_launch(void* const* d_in, const int* in_sizes, int n_in,
                              void* d_out, int out_size) {
    const float* x    = (const float*)d_in[0];
    const float* adj  = (const float*)d_in[1];
    const float* inxs = (const float*)d_in[2];
    const float* Wq   = (const float*)d_in[3];
    const float* Wk   = (const float*)d_in[4];
    const float* Wqs  = (const float*)d_in[5];
    const float* Wv   = (const float*)d_in[6];
    const float* nn_w = (const float*)d_in[7];
    const float* ns_w = (const float*)d_in[8];
    const float* Wqkv = (const float*)d_in[9];
    float* out = (float*)d_out;

    __half *pWh, *pxh, *pxl, *pqh, *pql, *pA2h, *pA2l, *pB2h, *pPh, *pVh;
    float *pProj, *pGq, *pLD; int* pIdx;
    cudaGetSymbolAddress((void**)&pWh,  gh_Wall);
    cudaGetSymbolAddress((void**)&pxh,  gh_x);
    cudaGetSymbolAddress((void**)&pxl,  gl_x);
    cudaGetSymbolAddress((void**)&pIdx, g_idx);
    cudaGetSymbolAddress((void**)&pProj, g_proj);
    cudaGetSymbolAddress((void**)&pqh,  gh_qmm);
    cudaGetSymbolAddress((void**)&pql,  gl_qmm);
    cudaGetSymbolAddress((void**)&pA2h, gh_A2);
    cudaGetSymbolAddress((void**)&pA2l, gl_A2);
    cudaGetSymbolAddress((void**)&pB2h, gh_B2);
    cudaGetSymbolAddress((void**)&pGq,  g_Gq);
    cudaGetSymbolAddress((void**)&pLD,  g_LD);
    cudaGetSymbolAddress((void**)&pPh,  gh_P);
    cudaGetSymbolAddress((void**)&pVh,  gh_Vt);

    cudaFuncSetAttribute(gemm_proj, cudaFuncAttributeMaxDynamicSharedMemorySize, SMEM_DYN);
    cudaFuncSetAttribute(gemm_mid,  cudaFuncAttributeMaxDynamicSharedMemorySize, SMEM_DYN);
    cudaFuncSetAttribute(gemm_out,  cudaFuncAttributeMaxDynamicSharedMemorySize, SMEM_DYN);

    prep_inputs<<<NB_PACKW + NB_CONVX + NB_EXIDX, 256>>>(
        Wq, Wk, Wqs, Wv, Wqkv, pWh, x, pxh, pxl, inxs, pIdx);

    // proj = x @ Wall^T : (4096 x 1792), K=256
    gemm_proj<<<dim3(NPROJ / 128, BT / 128, 1), 512, SMEM_DYN>>>();

    post_proj<<<NB_TRV + BT, 256>>>(pProj, pVh, pqh, pql);
    build_ab<<<BT, 256>>>(pProj, pIdx, pA2h, pA2l, pB2h, ns_w);

    // merged: L(+mask), Gq, D  — grid 4x4x24
    gemm_mid<<<dim3(4, 4, 24), 512, SMEM_DYN>>>(adj);

    simnn_softmax<<<dim3(Tt, Bb), 256>>>(pGq, pIdx, pLD, nn_w, pPh);

    // out: split-K=4 partials then reduce
    gemm_out<<<dim3(Cc / 128, Tt / 128, 32), 512, SMEM_DYN>>>();
    reduce_out<<<(int)(OUTN / 4 + 255) / 256, 256>>>(out);
}